// round 2
// baseline (speedup 1.0000x reference)
#include <cuda_runtime.h>
#include <math.h>

#define BATCH 4
#define SEQ   2048
#define HID   1024
#define NQKV  3072   // 3*HID

// Scratch (static device globals — no allocation)
__device__ float g_proj[(long)BATCH * SEQ * NQKV];        // [B*S, 3H]  ~100 MB
__device__ float g_scores[(long)BATCH * SEQ * SEQ];       // [B, S, S]  ~67 MB

// ---------------------------------------------------------------------------
// Tiled SGEMM with register prefetch + double-buffered smem.
//   C[z] = alpha * A[z] @ op(B[z]) + bias
//   TRANSB=false: B is [K,N] row-major -> C = A @ B
//   TRANSB=true : B is [N,K] row-major -> C = A @ B^T
// M % 128 == 0, N % 128 == 0, K % 16 == 0 (true for every call here).
// ---------------------------------------------------------------------------
template<bool TRANSB>
__global__ __launch_bounds__(256, 2)
void gemm_kernel(const float* __restrict__ A,
                 const float* __restrict__ Bm,
                 float* __restrict__ C,
                 const float* __restrict__ bias,   // length N or nullptr
                 int M, int N, int K,
                 int lda, int ldb, int ldc,
                 long strideAz, long strideBz, long strideCz,
                 float alpha)
{
    constexpr int BM = 128, BN = 128, BK = 16;
    constexpr int PAD = 4;                        // float4-aligned padded rows
    __shared__ float As[2][BK][BM + PAD];
    __shared__ float Bs[2][BK][BN + PAD];

    const int z = blockIdx.z;
    A  += (long)z * strideAz;
    Bm += (long)z * strideBz;
    C  += (long)z * strideCz;

    const int bm = blockIdx.y * BM;
    const int bn = blockIdx.x * BN;
    const int tid = threadIdx.x;
    const int tx = tid & 15;          // 0..15 -> N direction
    const int ty = tid >> 4;          // 0..15 -> M direction

    // --- per-thread load coordinates (invariant across K loop) ---
    // A tile (always [row=BM][k=BK], float4 along K, transposed into smem):
    int arow[2], akc[2];
    #pragma unroll
    for (int i = 0; i < 2; i++) {
        int f = tid + i * 256;
        arow[i] = f >> 2;             // 0..127
        akc[i]  = (f & 3) * 4;        // 0,4,8,12
    }
    // B tile:
    int br[2], bc[2];
    #pragma unroll
    for (int i = 0; i < 2; i++) {
        int f = tid + i * 256;
        if (TRANSB) { br[i] = f >> 2;  bc[i] = (f & 3) * 4; }   // n-row, k-col
        else        { br[i] = f >> 5;  bc[i] = (f & 31) * 4; }  // k-row, n-col
    }

    float acc[8][8];
    #pragma unroll
    for (int i = 0; i < 8; i++)
        #pragma unroll
        for (int j = 0; j < 8; j++)
            acc[i][j] = 0.0f;

    float4 ra[2], rb[2];

    // ---- prefetch tile 0 into registers
    #pragma unroll
    for (int i = 0; i < 2; i++)
        ra[i] = *(const float4*)(A + (long)(bm + arow[i]) * lda + akc[i]);
    #pragma unroll
    for (int i = 0; i < 2; i++) {
        if (TRANSB)
            rb[i] = *(const float4*)(Bm + (long)(bn + br[i]) * ldb + bc[i]);
        else
            rb[i] = *(const float4*)(Bm + (long)br[i] * ldb + bn + bc[i]);
    }

    // ---- store tile 0 into smem buffer 0
    #pragma unroll
    for (int i = 0; i < 2; i++) {
        As[0][akc[i] + 0][arow[i]] = ra[i].x;
        As[0][akc[i] + 1][arow[i]] = ra[i].y;
        As[0][akc[i] + 2][arow[i]] = ra[i].z;
        As[0][akc[i] + 3][arow[i]] = ra[i].w;
    }
    #pragma unroll
    for (int i = 0; i < 2; i++) {
        if (TRANSB) {
            Bs[0][bc[i] + 0][br[i]] = rb[i].x;
            Bs[0][bc[i] + 1][br[i]] = rb[i].y;
            Bs[0][bc[i] + 2][br[i]] = rb[i].z;
            Bs[0][bc[i] + 3][br[i]] = rb[i].w;
        } else {
            *(float4*)&Bs[0][br[i]][bc[i]] = rb[i];
        }
    }
    __syncthreads();

    int buf = 0;
    for (int k0 = BK; k0 <= K; k0 += BK) {
        const bool has_next = (k0 < K);

        // ---- issue global loads for the NEXT tile (overlap with compute)
        if (has_next) {
            #pragma unroll
            for (int i = 0; i < 2; i++)
                ra[i] = *(const float4*)(A + (long)(bm + arow[i]) * lda + k0 + akc[i]);
            #pragma unroll
            for (int i = 0; i < 2; i++) {
                if (TRANSB)
                    rb[i] = *(const float4*)(Bm + (long)(bn + br[i]) * ldb + k0 + bc[i]);
                else
                    rb[i] = *(const float4*)(Bm + (long)(k0 + br[i]) * ldb + bn + bc[i]);
            }
        }

        // ---- compute current tile from smem[buf]
        #pragma unroll
        for (int k = 0; k < BK; k++) {
            float a[8], b[8];
            *(float4*)(a + 0) = *(const float4*)&As[buf][k][ty * 8 + 0];
            *(float4*)(a + 4) = *(const float4*)&As[buf][k][ty * 8 + 4];
            *(float4*)(b + 0) = *(const float4*)&Bs[buf][k][tx * 8 + 0];
            *(float4*)(b + 4) = *(const float4*)&Bs[buf][k][tx * 8 + 4];
            #pragma unroll
            for (int i = 0; i < 8; i++)
                #pragma unroll
                for (int j = 0; j < 8; j++)
                    acc[i][j] = fmaf(a[i], b[j], acc[i][j]);
        }

        // ---- stage next tile into the other buffer, single barrier per tile
        if (has_next) {
            const int nb = buf ^ 1;
            #pragma unroll
            for (int i = 0; i < 2; i++) {
                As[nb][akc[i] + 0][arow[i]] = ra[i].x;
                As[nb][akc[i] + 1][arow[i]] = ra[i].y;
                As[nb][akc[i] + 2][arow[i]] = ra[i].z;
                As[nb][akc[i] + 3][arow[i]] = ra[i].w;
            }
            #pragma unroll
            for (int i = 0; i < 2; i++) {
                if (TRANSB) {
                    Bs[nb][bc[i] + 0][br[i]] = rb[i].x;
                    Bs[nb][bc[i] + 1][br[i]] = rb[i].y;
                    Bs[nb][bc[i] + 2][br[i]] = rb[i].z;
                    Bs[nb][bc[i] + 3][br[i]] = rb[i].w;
                } else {
                    *(float4*)&Bs[nb][br[i]][bc[i]] = rb[i];
                }
            }
            __syncthreads();
            buf = nb;
        }
    }

    // ---- epilogue
    #pragma unroll
    for (int i = 0; i < 8; i++) {
        int m = bm + ty * 8 + i;
        #pragma unroll
        for (int j = 0; j < 8; j += 4) {
            int n = bn + tx * 8 + j;
            float4 v;
            v.x = acc[i][j + 0] * alpha;
            v.y = acc[i][j + 1] * alpha;
            v.z = acc[i][j + 2] * alpha;
            v.w = acc[i][j + 3] * alpha;
            if (bias) {
                v.x += bias[n + 0];
                v.y += bias[n + 1];
                v.z += bias[n + 2];
                v.w += bias[n + 3];
            }
            *(float4*)(C + (long)m * ldc + n) = v;
        }
    }
}

// ---------------------------------------------------------------------------
// Row softmax over scores[row][0..S) with additive mask bias:
//   s += (1 - mask[b][k]) * -10000
// One 256-thread block per row; 8 elements per thread held in registers.
// ---------------------------------------------------------------------------
__global__ __launch_bounds__(256)
void softmax_kernel(float* __restrict__ scores, const float* __restrict__ mask)
{
    const int row = blockIdx.x;             // 0 .. B*S-1
    const int b   = row / SEQ;
    float* p = scores + (long)row * SEQ;
    const float* mrow = mask + (long)b * SEQ;

    const int tid = threadIdx.x;
    float v[8];
    float lmax = -INFINITY;
    #pragma unroll
    for (int i = 0; i < 8; i++) {
        int c = tid + i * 256;
        v[i] = p[c] + (1.0f - mrow[c]) * -10000.0f;
        lmax = fmaxf(lmax, v[i]);
    }

    __shared__ float red[32];
    #pragma unroll
    for (int o = 16; o > 0; o >>= 1)
        lmax = fmaxf(lmax, __shfl_xor_sync(0xFFFFFFFFu, lmax, o));
    if ((tid & 31) == 0) red[tid >> 5] = lmax;
    __syncthreads();
    if (tid < 32) {
        float m = (tid < 8) ? red[tid] : -INFINITY;
        #pragma unroll
        for (int o = 4; o > 0; o >>= 1)
            m = fmaxf(m, __shfl_xor_sync(0xFFFFFFFFu, m, o));
        if (tid == 0) red[0] = m;
    }
    __syncthreads();
    const float rmax = red[0];

    float lsum = 0.0f;
    #pragma unroll
    for (int i = 0; i < 8; i++) {
        v[i] = __expf(v[i] - rmax);
        lsum += v[i];
    }
    #pragma unroll
    for (int o = 16; o > 0; o >>= 1)
        lsum += __shfl_xor_sync(0xFFFFFFFFu, lsum, o);
    __syncthreads();
    if ((tid & 31) == 0) red[tid >> 5] = lsum;
    __syncthreads();
    if (tid < 32) {
        float s = (tid < 8) ? red[tid] : 0.0f;
        #pragma unroll
        for (int o = 4; o > 0; o >>= 1)
            s += __shfl_xor_sync(0xFFFFFFFFu, s, o);
        if (tid == 0) red[0] = s;
    }
    __syncthreads();
    const float inv = 1.0f / red[0];

    #pragma unroll
    for (int i = 0; i < 8; i++) {
        int c = tid + i * 256;
        p[c] = v[i] * inv;
    }
}

// ---------------------------------------------------------------------------
extern "C" void kernel_launch(void* const* d_in, const int* in_sizes, int n_in,
                              void* d_out, int out_size)
{
    const float* qkv   = (const float*)d_in[0];   // [B,S,H]
    const float* mask  = (const float*)d_in[1];   // [B,S]
    const float* W     = (const float*)d_in[2];   // [H,3H]
    const float* bqkv  = (const float*)d_in[3];   // [3H]
    float* out = (float*)d_out;                   // [B,S,H]

    float *proj, *scores;
    cudaGetSymbolAddress((void**)&proj,   g_proj);
    cudaGetSymbolAddress((void**)&scores, g_scores);

    const float scale = 1.0f / 32.0f;             // HID^-0.5 = 1/sqrt(1024)

    // 1) proj[B*S,3H] = qkv[B*S,H] @ W[H,3H] + b
    {
        dim3 grid(NQKV / 128, (BATCH * SEQ) / 128, 1);
        gemm_kernel<false><<<grid, 256>>>(qkv, W, proj, bqkv,
                                          BATCH * SEQ, NQKV, HID,
                                          HID, NQKV, NQKV,
                                          0, 0, 0, 1.0f);
    }
    // 2) scores[b] = scale * Q_b @ K_b^T   (Q = proj[:, 0:H], K = proj[:, H:2H])
    {
        dim3 grid(SEQ / 128, SEQ / 128, BATCH);
        gemm_kernel<true><<<grid, 256>>>(proj,             // Q base
                                         proj + HID,       // K base
                                         scores, nullptr,
                                         SEQ, SEQ, HID,
                                         NQKV, NQKV, SEQ,
                                         (long)SEQ * NQKV, (long)SEQ * NQKV, (long)SEQ * SEQ,
                                         scale);
    }
    // 3) softmax rows (with mask bias)
    softmax_kernel<<<BATCH * SEQ, 256>>>(scores, mask);

    // 4) out[b] = scores[b] @ V_b   (V = proj[:, 2H:3H])
    {
        dim3 grid(HID / 128, SEQ / 128, BATCH);
        gemm_kernel<false><<<grid, 256>>>(scores,
                                          proj + 2 * HID,
                                          out, nullptr,
                                          SEQ, HID, SEQ,
                                          SEQ, NQKV, HID,
                                          (long)SEQ * SEQ, (long)SEQ * NQKV, (long)SEQ * HID,
                                          1.0f);
    }
}

// round 8
// speedup vs baseline: 2.7195x; 2.7195x over previous
#include <cuda_runtime.h>
#include <cuda_bf16.h>
#include <math.h>
#include <stdint.h>

#define BATCH 4
#define SEQ   2048
#define HID   1024
#define NQKV  3072
#define MROWS (BATCH * SEQ)   // 8192

// ---------------- scratch (static device globals; no allocation) -----------
__device__ float g_proj[(long)MROWS * NQKV];                    // fp32 [8192,3072]
__device__ float g_scores[(long)BATCH * SEQ * SEQ];             // fp32 [4,2048,2048]
__device__ __nv_bfloat16 g_qkv_h[(long)MROWS * HID];
__device__ __nv_bfloat16 g_qkv_l[(long)MROWS * HID];
__device__ __nv_bfloat16 g_wt_h[(long)NQKV * HID];              // W^T [3072,1024]
__device__ __nv_bfloat16 g_wt_l[(long)NQKV * HID];
__device__ __nv_bfloat16 g_q_h[(long)MROWS * HID];
__device__ __nv_bfloat16 g_q_l[(long)MROWS * HID];
__device__ __nv_bfloat16 g_k_h[(long)MROWS * HID];
__device__ __nv_bfloat16 g_k_l[(long)MROWS * HID];
__device__ __nv_bfloat16 g_p_h[(long)BATCH * SEQ * SEQ];
__device__ __nv_bfloat16 g_p_l[(long)BATCH * SEQ * SEQ];
__device__ __nv_bfloat16 g_vt_h[(long)BATCH * HID * SEQ];       // V^T per batch [1024,2048]
__device__ __nv_bfloat16 g_vt_l[(long)BATCH * HID * SEQ];

// ---------------- base-target PTX helpers (sm_80+, no 'a' features) --------
__device__ __forceinline__ void cp16(uint32_t dst, const void* src) {
    asm volatile("cp.async.cg.shared.global [%0], [%1], 16;" :: "r"(dst), "l"(src));
}
#define CP_COMMIT() asm volatile("cp.async.commit_group;" ::: "memory")
#define CP_WAIT1()  asm volatile("cp.async.wait_group 1;" ::: "memory")
#define CP_WAIT0()  asm volatile("cp.async.wait_group 0;" ::: "memory")

__device__ __forceinline__ uint32_t smem_to_u32(const void* p) {
    uint32_t a;
    asm("{ .reg .u64 t; cvta.to.shared.u64 t, %1; cvt.u32.u64 %0, t; }" : "=r"(a) : "l"(p));
    return a;
}
__device__ __forceinline__ uint32_t sw128(uint32_t off) {
    return off ^ ((off >> 3) & 0x70);
}
__device__ __forceinline__ void ldsm4(uint32_t& r0, uint32_t& r1, uint32_t& r2, uint32_t& r3,
                                      uint32_t addr) {
    asm volatile("ldmatrix.sync.aligned.m8n8.x4.shared.b16 {%0,%1,%2,%3}, [%4];"
                 : "=r"(r0), "=r"(r1), "=r"(r2), "=r"(r3) : "r"(addr));
}
__device__ __forceinline__ void mma_bf16(float* c, const uint32_t* a, const uint32_t* b) {
    asm volatile("mma.sync.aligned.m16n8k16.row.col.f32.bf16.bf16.f32 "
                 "{%0,%1,%2,%3}, {%4,%5,%6,%7}, {%8,%9}, {%0,%1,%2,%3};"
                 : "+f"(c[0]), "+f"(c[1]), "+f"(c[2]), "+f"(c[3])
                 : "r"(a[0]), "r"(a[1]), "r"(a[2]), "r"(a[3]), "r"(b[0]), "r"(b[1]));
}

// ---------------- split-bf16 tensor-core GEMM ------------------------------
// C[z][M,N] = alpha * (Ah+Al)[z] @ (Bh+Bl)[z]^T + bias
// A: [M,K] row-major bf16; B: [N,K] row-major bf16. K % 64 == 0.
// grid = (N/128, M/128, Z), 256 threads (8 warps, each 64x32 of the 128x128 tile).
static constexpr int TILE_B   = 128 * 128;      // 16 KB: 128 rows x 128B (64 bf16)
static constexpr int BUF_B    = 4 * TILE_B;     // Ah, Al, Bh, Bl
static constexpr int GEMM_SMEM = 2 * BUF_B;     // 131072 double-buffered

__device__ __forceinline__ void load_tile_async(uint32_t smem_tile,
                                                const __nv_bfloat16* gbase,
                                                int ld, int k0, int tid) {
    #pragma unroll
    for (int t = 0; t < 4; t++) {
        int cid = tid + t * 256;          // 0..1023
        int row = cid >> 3;               // 0..127
        int ce  = (cid & 7) * 8;          // element offset (16B chunks)
        cp16(smem_tile + sw128(row * 128 + ce * 2),
             gbase + (long)row * ld + k0 + ce);
    }
}

__global__ __launch_bounds__(256)
void gemm_mma_kernel(const __nv_bfloat16* __restrict__ Ah, const __nv_bfloat16* __restrict__ Al,
                     const __nv_bfloat16* __restrict__ Bh, const __nv_bfloat16* __restrict__ Bl,
                     float* __restrict__ C, const float* __restrict__ bias,
                     int K, int lda, int ldb, int ldc,
                     long sAz, long sBz, long sCz, float alpha)
{
    extern __shared__ char smem[];
    const uint32_t sb = smem_to_u32(smem);
    const int tid  = threadIdx.x;
    const int wid  = tid >> 5;
    const int lane = tid & 31;
    const int z  = blockIdx.z;
    const int bm = blockIdx.y * 128;
    const int bn = blockIdx.x * 128;

    const __nv_bfloat16* ah = Ah + (long)z * sAz + (long)bm * lda;
    const __nv_bfloat16* al = Al + (long)z * sAz + (long)bm * lda;
    const __nv_bfloat16* bh = Bh + (long)z * sBz + (long)bn * ldb;
    const __nv_bfloat16* bl = Bl + (long)z * sBz + (long)bn * ldb;

    const int wm = (wid & 1) * 64;        // warp M offset in tile
    const int wn = (wid >> 1) * 32;       // warp N offset in tile

    float acc[4][4][4];
    #pragma unroll
    for (int i = 0; i < 4; i++)
        #pragma unroll
        for (int j = 0; j < 4; j++)
            #pragma unroll
            for (int r = 0; r < 4; r++)
                acc[i][j][r] = 0.0f;

    // prologue: chunk 0 -> buffer 0
    load_tile_async(sb + 0 * TILE_B, ah, lda, 0, tid);
    load_tile_async(sb + 1 * TILE_B, al, lda, 0, tid);
    load_tile_async(sb + 2 * TILE_B, bh, ldb, 0, tid);
    load_tile_async(sb + 3 * TILE_B, bl, ldb, 0, tid);
    CP_COMMIT();

    const int NC = K >> 6;
    for (int c = 0; c < NC; c++) {
        const int b = c & 1;
        if (c + 1 < NC) {
            const uint32_t nb = ((c + 1) & 1) * BUF_B;
            const int k0 = (c + 1) << 6;
            load_tile_async(sb + nb + 0 * TILE_B, ah, lda, k0, tid);
            load_tile_async(sb + nb + 1 * TILE_B, al, lda, k0, tid);
            load_tile_async(sb + nb + 2 * TILE_B, bh, ldb, k0, tid);
            load_tile_async(sb + nb + 3 * TILE_B, bl, ldb, k0, tid);
            CP_COMMIT();
            CP_WAIT1();
        } else {
            CP_WAIT0();
        }
        __syncthreads();

        const uint32_t tAh = sb + b * BUF_B;
        const uint32_t tAl = tAh + TILE_B;
        const uint32_t tBh = tAl + TILE_B;
        const uint32_t tBl = tBh + TILE_B;

        #pragma unroll
        for (int ks = 0; ks < 4; ks++) {
            uint32_t ahf[4][4], alf[4][4], bhf[4][2], blf[4][2];
            // A fragments: 4 m16 tiles; canonical ldmatrix.x4 addressing
            #pragma unroll
            for (int i = 0; i < 4; i++) {
                int row = wm + i * 16 + (lane & 15);
                uint32_t off = sw128(row * 128 + ks * 32 + (lane >> 4) * 16);
                ldsm4(ahf[i][0], ahf[i][1], ahf[i][2], ahf[i][3], tAh + off);
                ldsm4(alf[i][0], alf[i][1], alf[i][2], alf[i][3], tAl + off);
            }
            // B fragments: 4 n8 tiles via two ldmatrix.x4 (B stored [n][k])
            #pragma unroll
            for (int jj = 0; jj < 2; jj++) {
                int nrow = wn + jj * 16 + (lane >> 4) * 8 + (lane & 7);
                uint32_t off = sw128(nrow * 128 + ks * 32 + ((lane >> 3) & 1) * 16);
                ldsm4(bhf[jj * 2][0], bhf[jj * 2][1], bhf[jj * 2 + 1][0], bhf[jj * 2 + 1][1],
                      tBh + off);
                ldsm4(blf[jj * 2][0], blf[jj * 2][1], blf[jj * 2 + 1][0], blf[jj * 2 + 1][1],
                      tBl + off);
            }
            // 3-term compensated products, fp32 accumulate
            #pragma unroll
            for (int i = 0; i < 4; i++)
                #pragma unroll
                for (int j = 0; j < 4; j++) {
                    mma_bf16(acc[i][j], ahf[i], bhf[j]);
                    mma_bf16(acc[i][j], ahf[i], blf[j]);
                    mma_bf16(acc[i][j], alf[i], bhf[j]);
                }
        }
        __syncthreads();
    }

    // epilogue: lane gid holds rows gid/gid+8, cols 2*tig..+1 of each 16x8 frag
    const int gid = lane >> 2;
    const int tig = lane & 3;
    float* Cz = C + (long)z * sCz;
    #pragma unroll
    for (int i = 0; i < 4; i++) {
        #pragma unroll
        for (int j = 0; j < 4; j++) {
            int r0 = bm + wm + i * 16 + gid;
            int c0 = bn + wn + j * 8 + tig * 2;
            float bx = bias ? bias[c0] : 0.0f;
            float by = bias ? bias[c0 + 1] : 0.0f;
            float2 v0 = make_float2(acc[i][j][0] * alpha + bx, acc[i][j][1] * alpha + by);
            float2 v1 = make_float2(acc[i][j][2] * alpha + bx, acc[i][j][3] * alpha + by);
            *reinterpret_cast<float2*>(Cz + (long)r0 * ldc + c0) = v0;
            *reinterpret_cast<float2*>(Cz + (long)(r0 + 8) * ldc + c0) = v1;
        }
    }
}

// ---------------- fp32 -> (hi,lo) bf16 split ------------------------------
__device__ __forceinline__ void split4(float4 v, __nv_bfloat16* h, __nv_bfloat16* l) {
    h[0] = __float2bfloat16(v.x); l[0] = __float2bfloat16(v.x - __bfloat162float(h[0]));
    h[1] = __float2bfloat16(v.y); l[1] = __float2bfloat16(v.y - __bfloat162float(h[1]));
    h[2] = __float2bfloat16(v.z); l[2] = __float2bfloat16(v.z - __bfloat162float(h[2]));
    h[3] = __float2bfloat16(v.w); l[3] = __float2bfloat16(v.w - __bfloat162float(h[3]));
}

__global__ __launch_bounds__(256)
void split_kernel(const float* __restrict__ in, int ldi,
                  __nv_bfloat16* __restrict__ oh, __nv_bfloat16* __restrict__ ol,
                  int ldo, int cols4)
{
    long t = (long)blockIdx.x * 256 + threadIdx.x;
    int row = (int)(t / cols4);
    int cq  = (int)(t % cols4);
    float4 v = *reinterpret_cast<const float4*>(in + (long)row * ldi + cq * 4);
    __nv_bfloat16 h[4], l[4];
    split4(v, h, l);
    *reinterpret_cast<uint2*>(oh + (long)row * ldo + cq * 4) = *reinterpret_cast<uint2*>(h);
    *reinterpret_cast<uint2*>(ol + (long)row * ldo + cq * 4) = *reinterpret_cast<uint2*>(l);
}

// ---------------- fp32 transpose + split: out[c][r] = in[r][c] ------------
__global__ __launch_bounds__(256)
void transpose_split_kernel(const float* __restrict__ in, long inZ, int ldi,
                            __nv_bfloat16* __restrict__ oh, __nv_bfloat16* __restrict__ ol,
                            long outZ, int ldo)
{
    __shared__ float t[32][33];
    const float* src = in + (long)blockIdx.z * inZ;
    int r0 = blockIdx.y * 32, c0 = blockIdx.x * 32;
    int tx = threadIdx.x & 31, ty = threadIdx.x >> 5;   // 32x8
    #pragma unroll
    for (int j = 0; j < 32; j += 8)
        t[ty + j][tx] = src[(long)(r0 + ty + j) * ldi + c0 + tx];
    __syncthreads();
    long zo = (long)blockIdx.z * outZ;
    #pragma unroll
    for (int j = 0; j < 32; j += 8) {
        float x = t[tx][ty + j];
        __nv_bfloat16 h = __float2bfloat16(x);
        __nv_bfloat16 l = __float2bfloat16(x - __bfloat162float(h));
        long o = zo + (long)(c0 + ty + j) * ldo + r0 + tx;
        oh[o] = h; ol[o] = l;
    }
}

// ---------------- softmax + split to bf16 hi/lo ---------------------------
__global__ __launch_bounds__(256)
void softmax_split_kernel(const float* __restrict__ scores, const float* __restrict__ mask,
                          __nv_bfloat16* __restrict__ ph, __nv_bfloat16* __restrict__ pl)
{
    const int row = blockIdx.x;
    const int b   = row / SEQ;
    const float* p = scores + (long)row * SEQ;
    const float* mrow = mask + (long)b * SEQ;
    const int tid = threadIdx.x;

    float v[8];
    float lmax = -INFINITY;
    #pragma unroll
    for (int i = 0; i < 8; i++) {
        int c = tid + i * 256;
        v[i] = p[c] + (1.0f - mrow[c]) * -10000.0f;
        lmax = fmaxf(lmax, v[i]);
    }
    __shared__ float red[32];
    #pragma unroll
    for (int o = 16; o > 0; o >>= 1)
        lmax = fmaxf(lmax, __shfl_xor_sync(0xFFFFFFFFu, lmax, o));
    if ((tid & 31) == 0) red[tid >> 5] = lmax;
    __syncthreads();
    if (tid < 32) {
        float m = (tid < 8) ? red[tid] : -INFINITY;
        #pragma unroll
        for (int o = 4; o > 0; o >>= 1)
            m = fmaxf(m, __shfl_xor_sync(0xFFFFFFFFu, m, o));
        if (tid == 0) red[0] = m;
    }
    __syncthreads();
    const float rmax = red[0];

    float lsum = 0.0f;
    #pragma unroll
    for (int i = 0; i < 8; i++) {
        v[i] = __expf(v[i] - rmax);
        lsum += v[i];
    }
    #pragma unroll
    for (int o = 16; o > 0; o >>= 1)
        lsum += __shfl_xor_sync(0xFFFFFFFFu, lsum, o);
    __syncthreads();
    if ((tid & 31) == 0) red[tid >> 5] = lsum;
    __syncthreads();
    if (tid < 32) {
        float s = (tid < 8) ? red[tid] : 0.0f;
        #pragma unroll
        for (int o = 4; o > 0; o >>= 1)
            s += __shfl_xor_sync(0xFFFFFFFFu, s, o);
        if (tid == 0) red[0] = s;
    }
    __syncthreads();
    const float inv = 1.0f / red[0];

    #pragma unroll
    for (int i = 0; i < 8; i++) {
        int c = tid + i * 256;
        float x = v[i] * inv;
        __nv_bfloat16 h = __float2bfloat16(x);
        __nv_bfloat16 l = __float2bfloat16(x - __bfloat162float(h));
        ph[(long)row * SEQ + c] = h;
        pl[(long)row * SEQ + c] = l;
    }
}

// ---------------------------------------------------------------------------
extern "C" void kernel_launch(void* const* d_in, const int* in_sizes, int n_in,
                              void* d_out, int out_size)
{
    const float* qkv  = (const float*)d_in[0];
    const float* mask = (const float*)d_in[1];
    const float* W    = (const float*)d_in[2];
    const float* bqkv = (const float*)d_in[3];
    float* out = (float*)d_out;

    float *proj, *scores;
    __nv_bfloat16 *qkvh, *qkvl, *wth, *wtl, *qh, *ql, *kh, *kl, *pph, *ppl, *vth, *vtl;
    cudaGetSymbolAddress((void**)&proj, g_proj);
    cudaGetSymbolAddress((void**)&scores, g_scores);
    cudaGetSymbolAddress((void**)&qkvh, g_qkv_h);  cudaGetSymbolAddress((void**)&qkvl, g_qkv_l);
    cudaGetSymbolAddress((void**)&wth, g_wt_h);    cudaGetSymbolAddress((void**)&wtl, g_wt_l);
    cudaGetSymbolAddress((void**)&qh, g_q_h);      cudaGetSymbolAddress((void**)&ql, g_q_l);
    cudaGetSymbolAddress((void**)&kh, g_k_h);      cudaGetSymbolAddress((void**)&kl, g_k_l);
    cudaGetSymbolAddress((void**)&pph, g_p_h);     cudaGetSymbolAddress((void**)&ppl, g_p_l);
    cudaGetSymbolAddress((void**)&vth, g_vt_h);    cudaGetSymbolAddress((void**)&vtl, g_vt_l);

    cudaFuncSetAttribute(gemm_mma_kernel,
                         cudaFuncAttributeMaxDynamicSharedMemorySize, GEMM_SMEM);

    // 1) split qkv -> bf16 hi/lo
    split_kernel<<<(long)MROWS * (HID / 4) / 256, 256>>>(qkv, HID, qkvh, qkvl, HID, HID / 4);
    // 2) W [1024,3072] -> W^T [3072,1024] hi/lo
    transpose_split_kernel<<<dim3(NQKV / 32, HID / 32, 1), 256>>>(W, 0, NQKV, wth, wtl, 0, HID);
    // 3) proj = qkv @ W + b   (M=8192, N=3072, K=1024)
    gemm_mma_kernel<<<dim3(NQKV / 128, MROWS / 128, 1), 256, GEMM_SMEM>>>(
        qkvh, qkvl, wth, wtl, proj, bqkv, HID, HID, HID, NQKV, 0, 0, 0, 1.0f);
    // 4/5) split Q and K slices of proj
    split_kernel<<<(long)MROWS * (HID / 4) / 256, 256>>>(proj,       NQKV, qh, ql, HID, HID / 4);
    split_kernel<<<(long)MROWS * (HID / 4) / 256, 256>>>(proj + HID, NQKV, kh, kl, HID, HID / 4);
    // 6) V slices -> V^T per batch [1024,2048] hi/lo
    transpose_split_kernel<<<dim3(HID / 32, SEQ / 32, BATCH), 256>>>(
        proj + 2 * HID, (long)SEQ * NQKV, NQKV, vth, vtl, (long)HID * SEQ, SEQ);
    // 7) scores[b] = (1/32) * Q_b @ K_b^T   (M=2048, N=2048, K=1024)
    gemm_mma_kernel<<<dim3(SEQ / 128, SEQ / 128, BATCH), 256, GEMM_SMEM>>>(
        qh, ql, kh, kl, scores, nullptr, HID, HID, HID, SEQ,
        (long)SEQ * HID, (long)SEQ * HID, (long)SEQ * SEQ, 1.0f / 32.0f);
    // 8) softmax rows + split P -> bf16 hi/lo
    softmax_split_kernel<<<BATCH * SEQ, 256>>>(scores, mask, pph, ppl);
    // 9) out[b] = P_b @ V_b   (M=2048, N=1024, K=2048)
    gemm_mma_kernel<<<dim3(HID / 128, SEQ / 128, BATCH), 256, GEMM_SMEM>>>(
        pph, ppl, vth, vtl, out, nullptr, SEQ, SEQ, SEQ, HID,
        (long)SEQ * SEQ, (long)HID * SEQ, (long)SEQ * HID, 1.0f);
}

// round 9
// speedup vs baseline: 2.7761x; 1.0208x over previous
#include <cuda_runtime.h>
#include <cuda_bf16.h>
#include <math.h>
#include <stdint.h>

#define BATCH 4
#define SEQ   2048
#define HID   1024
#define NQKV  3072
#define MROWS (BATCH * SEQ)   // 8192

// ---------------- scratch (static device globals; no allocation) -----------
__device__ float g_proj[(long)MROWS * NQKV];                    // fp32 [8192,3072] (V region used)
__device__ float g_scores[(long)BATCH * SEQ * SEQ];             // fp32 [4,2048,2048]
__device__ __nv_bfloat16 g_qkv_h[(long)MROWS * HID];
__device__ __nv_bfloat16 g_qkv_l[(long)MROWS * HID];
__device__ __nv_bfloat16 g_wt_h[(long)NQKV * HID];              // W^T [3072,1024]
__device__ __nv_bfloat16 g_wt_l[(long)NQKV * HID];
__device__ __nv_bfloat16 g_q_h[(long)MROWS * HID];
__device__ __nv_bfloat16 g_q_l[(long)MROWS * HID];
__device__ __nv_bfloat16 g_k_h[(long)MROWS * HID];
__device__ __nv_bfloat16 g_k_l[(long)MROWS * HID];
__device__ __nv_bfloat16 g_p_h[(long)BATCH * SEQ * SEQ];
__device__ __nv_bfloat16 g_p_l[(long)BATCH * SEQ * SEQ];
__device__ __nv_bfloat16 g_vt_h[(long)BATCH * HID * SEQ];       // V^T per batch [1024,2048]
__device__ __nv_bfloat16 g_vt_l[(long)BATCH * HID * SEQ];

// ---------------- base-target PTX helpers (sm_80+, no 'a' features) --------
__device__ __forceinline__ void cp16(uint32_t dst, const void* src) {
    asm volatile("cp.async.cg.shared.global [%0], [%1], 16;" :: "r"(dst), "l"(src));
}
#define CP_COMMIT() asm volatile("cp.async.commit_group;" ::: "memory")
#define CP_WAIT1()  asm volatile("cp.async.wait_group 1;" ::: "memory")
#define CP_WAIT0()  asm volatile("cp.async.wait_group 0;" ::: "memory")

__device__ __forceinline__ uint32_t smem_to_u32(const void* p) {
    uint32_t a;
    asm("{ .reg .u64 t; cvta.to.shared.u64 t, %1; cvt.u32.u64 %0, t; }" : "=r"(a) : "l"(p));
    return a;
}
__device__ __forceinline__ uint32_t sw128(uint32_t off) {
    return off ^ ((off >> 3) & 0x70);
}
__device__ __forceinline__ void ldsm4(uint32_t& r0, uint32_t& r1, uint32_t& r2, uint32_t& r3,
                                      uint32_t addr) {
    asm volatile("ldmatrix.sync.aligned.m8n8.x4.shared.b16 {%0,%1,%2,%3}, [%4];"
                 : "=r"(r0), "=r"(r1), "=r"(r2), "=r"(r3) : "r"(addr));
}
__device__ __forceinline__ void mma_bf16(float* c, const uint32_t* a, const uint32_t* b) {
    asm volatile("mma.sync.aligned.m16n8k16.row.col.f32.bf16.bf16.f32 "
                 "{%0,%1,%2,%3}, {%4,%5,%6,%7}, {%8,%9}, {%0,%1,%2,%3};"
                 : "+f"(c[0]), "+f"(c[1]), "+f"(c[2]), "+f"(c[3])
                 : "r"(a[0]), "r"(a[1]), "r"(a[2]), "r"(a[3]), "r"(b[0]), "r"(b[1]));
}
__device__ __forceinline__ __nv_bfloat162 split2(float x, float y, __nv_bfloat162& lo) {
    __nv_bfloat16 hx = __float2bfloat16(x);
    __nv_bfloat16 hy = __float2bfloat16(y);
    lo = __nv_bfloat162(__float2bfloat16(x - __bfloat162float(hx)),
                        __float2bfloat16(y - __bfloat162float(hy)));
    return __nv_bfloat162(hx, hy);
}

// ---------------- split-bf16 tensor-core GEMM ------------------------------
// C[z][M,N] = alpha * (Ah+Al)[z] @ (Bh+Bl)[z]^T + bias
// A: [M,K] row-major bf16; B: [N,K] row-major bf16. K % 64 == 0.
// grid = (N/128, M/128, Z), 256 threads (8 warps, each 64x32 of the 128x128 tile).
// If QH != nullptr (QKV-proj mode, N=3072): output cols [0,1024) are written as
// hi/lo bf16 to QH/QL, [1024,2048) to KH/KL (ld=HID), and NOT to C; cols
// [2048,3072) (V) go to C as fp32. Region is uniform per CTA (1024 % 128 == 0).
static constexpr int TILE_B   = 128 * 128;      // 16 KB: 128 rows x 128B (64 bf16)
static constexpr int BUF_B    = 4 * TILE_B;     // Ah, Al, Bh, Bl
static constexpr int GEMM_SMEM = 2 * BUF_B;     // 131072 double-buffered

__device__ __forceinline__ void load_tile_async(uint32_t smem_tile,
                                                const __nv_bfloat16* gbase,
                                                int ld, int k0, int tid) {
    #pragma unroll
    for (int t = 0; t < 4; t++) {
        int cid = tid + t * 256;          // 0..1023
        int row = cid >> 3;               // 0..127
        int ce  = (cid & 7) * 8;          // element offset (16B chunks)
        cp16(smem_tile + sw128(row * 128 + ce * 2),
             gbase + (long)row * ld + k0 + ce);
    }
}

__global__ __launch_bounds__(256)
void gemm_mma_kernel(const __nv_bfloat16* __restrict__ Ah, const __nv_bfloat16* __restrict__ Al,
                     const __nv_bfloat16* __restrict__ Bh, const __nv_bfloat16* __restrict__ Bl,
                     float* __restrict__ C, const float* __restrict__ bias,
                     __nv_bfloat16* __restrict__ QH, __nv_bfloat16* __restrict__ QL,
                     __nv_bfloat16* __restrict__ KH, __nv_bfloat16* __restrict__ KL,
                     int K, int lda, int ldb, int ldc,
                     long sAz, long sBz, long sCz, float alpha)
{
    extern __shared__ char smem[];
    const uint32_t sb = smem_to_u32(smem);
    const int tid  = threadIdx.x;
    const int wid  = tid >> 5;
    const int lane = tid & 31;
    const int z  = blockIdx.z;
    const int bm = blockIdx.y * 128;
    const int bn = blockIdx.x * 128;

    const __nv_bfloat16* ah = Ah + (long)z * sAz + (long)bm * lda;
    const __nv_bfloat16* al = Al + (long)z * sAz + (long)bm * lda;
    const __nv_bfloat16* bh = Bh + (long)z * sBz + (long)bn * ldb;
    const __nv_bfloat16* bl = Bl + (long)z * sBz + (long)bn * ldb;

    const int wm = (wid & 1) * 64;        // warp M offset in tile
    const int wn = (wid >> 1) * 32;       // warp N offset in tile

    float acc[4][4][4];
    #pragma unroll
    for (int i = 0; i < 4; i++)
        #pragma unroll
        for (int j = 0; j < 4; j++)
            #pragma unroll
            for (int r = 0; r < 4; r++)
                acc[i][j][r] = 0.0f;

    // prologue: chunk 0 -> buffer 0
    load_tile_async(sb + 0 * TILE_B, ah, lda, 0, tid);
    load_tile_async(sb + 1 * TILE_B, al, lda, 0, tid);
    load_tile_async(sb + 2 * TILE_B, bh, ldb, 0, tid);
    load_tile_async(sb + 3 * TILE_B, bl, ldb, 0, tid);
    CP_COMMIT();

    const int NC = K >> 6;
    for (int c = 0; c < NC; c++) {
        const int b = c & 1;
        if (c + 1 < NC) {
            const uint32_t nb = ((c + 1) & 1) * BUF_B;
            const int k0 = (c + 1) << 6;
            load_tile_async(sb + nb + 0 * TILE_B, ah, lda, k0, tid);
            load_tile_async(sb + nb + 1 * TILE_B, al, lda, k0, tid);
            load_tile_async(sb + nb + 2 * TILE_B, bh, ldb, k0, tid);
            load_tile_async(sb + nb + 3 * TILE_B, bl, ldb, k0, tid);
            CP_COMMIT();
            CP_WAIT1();
        } else {
            CP_WAIT0();
        }
        __syncthreads();

        const uint32_t tAh = sb + b * BUF_B;
        const uint32_t tAl = tAh + TILE_B;
        const uint32_t tBh = tAl + TILE_B;
        const uint32_t tBl = tBh + TILE_B;

        #pragma unroll
        for (int ks = 0; ks < 4; ks++) {
            uint32_t ahf[4][4], alf[4][4], bhf[4][2], blf[4][2];
            // A fragments: 4 m16 tiles; canonical ldmatrix.x4 addressing
            #pragma unroll
            for (int i = 0; i < 4; i++) {
                int row = wm + i * 16 + (lane & 15);
                uint32_t off = sw128(row * 128 + ks * 32 + (lane >> 4) * 16);
                ldsm4(ahf[i][0], ahf[i][1], ahf[i][2], ahf[i][3], tAh + off);
                ldsm4(alf[i][0], alf[i][1], alf[i][2], alf[i][3], tAl + off);
            }
            // B fragments: 4 n8 tiles via two ldmatrix.x4 (B stored [n][k])
            #pragma unroll
            for (int jj = 0; jj < 2; jj++) {
                int nrow = wn + jj * 16 + (lane >> 4) * 8 + (lane & 7);
                uint32_t off = sw128(nrow * 128 + ks * 32 + ((lane >> 3) & 1) * 16);
                ldsm4(bhf[jj * 2][0], bhf[jj * 2][1], bhf[jj * 2 + 1][0], bhf[jj * 2 + 1][1],
                      tBh + off);
                ldsm4(blf[jj * 2][0], blf[jj * 2][1], blf[jj * 2 + 1][0], blf[jj * 2 + 1][1],
                      tBl + off);
            }
            // term-major sweeps: 16 independent HMMAs between accumulator reuse
            #pragma unroll
            for (int i = 0; i < 4; i++)
                #pragma unroll
                for (int j = 0; j < 4; j++)
                    mma_bf16(acc[i][j], ahf[i], bhf[j]);
            #pragma unroll
            for (int i = 0; i < 4; i++)
                #pragma unroll
                for (int j = 0; j < 4; j++)
                    mma_bf16(acc[i][j], ahf[i], blf[j]);
            #pragma unroll
            for (int i = 0; i < 4; i++)
                #pragma unroll
                for (int j = 0; j < 4; j++)
                    mma_bf16(acc[i][j], alf[i], bhf[j]);
        }
        __syncthreads();
    }

    // epilogue: lane gid holds rows gid/gid+8, cols 2*tig..+1 of each 16x8 frag
    const int gid = lane >> 2;
    const int tig = lane & 3;
    const int region = (QH != nullptr) ? (bn >> 10) : 2;   // 0=Q, 1=K, 2=fp32->C

    if (region < 2) {
        // QKV-proj Q/K region: write hi/lo bf16 pairs directly (ld = HID)
        __nv_bfloat16* oh = region ? KH : QH;
        __nv_bfloat16* ol = region ? KL : QL;
        const int cb = bn - (region << 10);
        #pragma unroll
        for (int i = 0; i < 4; i++) {
            #pragma unroll
            for (int j = 0; j < 4; j++) {
                int r0 = bm + wm + i * 16 + gid;
                int c0 = cb + wn + j * 8 + tig * 2;
                int cg = c0 + (region << 10);   // bias index in [0,3072)
                float bx = bias[cg], by = bias[cg + 1];
                float x0 = acc[i][j][0] * alpha + bx, y0 = acc[i][j][1] * alpha + by;
                float x1 = acc[i][j][2] * alpha + bx, y1 = acc[i][j][3] * alpha + by;
                __nv_bfloat162 l0, l1;
                __nv_bfloat162 h0 = split2(x0, y0, l0);
                __nv_bfloat162 h1 = split2(x1, y1, l1);
                *reinterpret_cast<__nv_bfloat162*>(oh + (long)r0 * HID + c0) = h0;
                *reinterpret_cast<__nv_bfloat162*>(ol + (long)r0 * HID + c0) = l0;
                *reinterpret_cast<__nv_bfloat162*>(oh + (long)(r0 + 8) * HID + c0) = h1;
                *reinterpret_cast<__nv_bfloat162*>(ol + (long)(r0 + 8) * HID + c0) = l1;
            }
        }
    } else {
        float* Cz = C + (long)z * sCz;
        #pragma unroll
        for (int i = 0; i < 4; i++) {
            #pragma unroll
            for (int j = 0; j < 4; j++) {
                int r0 = bm + wm + i * 16 + gid;
                int c0 = bn + wn + j * 8 + tig * 2;
                float bx = bias ? bias[c0] : 0.0f;
                float by = bias ? bias[c0 + 1] : 0.0f;
                float2 v0 = make_float2(acc[i][j][0] * alpha + bx, acc[i][j][1] * alpha + by);
                float2 v1 = make_float2(acc[i][j][2] * alpha + bx, acc[i][j][3] * alpha + by);
                *reinterpret_cast<float2*>(Cz + (long)r0 * ldc + c0) = v0;
                *reinterpret_cast<float2*>(Cz + (long)(r0 + 8) * ldc + c0) = v1;
            }
        }
    }
}

// ---------------- fp32 -> (hi,lo) bf16 split ------------------------------
__device__ __forceinline__ void split4(float4 v, __nv_bfloat16* h, __nv_bfloat16* l) {
    h[0] = __float2bfloat16(v.x); l[0] = __float2bfloat16(v.x - __bfloat162float(h[0]));
    h[1] = __float2bfloat16(v.y); l[1] = __float2bfloat16(v.y - __bfloat162float(h[1]));
    h[2] = __float2bfloat16(v.z); l[2] = __float2bfloat16(v.z - __bfloat162float(h[2]));
    h[3] = __float2bfloat16(v.w); l[3] = __float2bfloat16(v.w - __bfloat162float(h[3]));
}

__global__ __launch_bounds__(256)
void split_kernel(const float* __restrict__ in, int ldi,
                  __nv_bfloat16* __restrict__ oh, __nv_bfloat16* __restrict__ ol,
                  int ldo, int cols4)
{
    long t = (long)blockIdx.x * 256 + threadIdx.x;
    int row = (int)(t / cols4);
    int cq  = (int)(t % cols4);
    float4 v = *reinterpret_cast<const float4*>(in + (long)row * ldi + cq * 4);
    __nv_bfloat16 h[4], l[4];
    split4(v, h, l);
    *reinterpret_cast<uint2*>(oh + (long)row * ldo + cq * 4) = *reinterpret_cast<uint2*>(h);
    *reinterpret_cast<uint2*>(ol + (long)row * ldo + cq * 4) = *reinterpret_cast<uint2*>(l);
}

// ---------------- fp32 transpose + split: out[c][r] = in[r][c] ------------
__global__ __launch_bounds__(256)
void transpose_split_kernel(const float* __restrict__ in, long inZ, int ldi,
                            __nv_bfloat16* __restrict__ oh, __nv_bfloat16* __restrict__ ol,
                            long outZ, int ldo)
{
    __shared__ float t[32][33];
    const float* src = in + (long)blockIdx.z * inZ;
    int r0 = blockIdx.y * 32, c0 = blockIdx.x * 32;
    int tx = threadIdx.x & 31, ty = threadIdx.x >> 5;   // 32x8
    #pragma unroll
    for (int j = 0; j < 32; j += 8)
        t[ty + j][tx] = src[(long)(r0 + ty + j) * ldi + c0 + tx];
    __syncthreads();
    long zo = (long)blockIdx.z * outZ;
    #pragma unroll
    for (int j = 0; j < 32; j += 8) {
        float x = t[tx][ty + j];
        __nv_bfloat16 h = __float2bfloat16(x);
        __nv_bfloat16 l = __float2bfloat16(x - __bfloat162float(h));
        long o = zo + (long)(c0 + ty + j) * ldo + r0 + tx;
        oh[o] = h; ol[o] = l;
    }
}

// ---------------- softmax + split to bf16 hi/lo ---------------------------
__global__ __launch_bounds__(256)
void softmax_split_kernel(const float* __restrict__ scores, const float* __restrict__ mask,
                          __nv_bfloat16* __restrict__ ph, __nv_bfloat16* __restrict__ pl)
{
    const int row = blockIdx.x;
    const int b   = row / SEQ;
    const float* p = scores + (long)row * SEQ;
    const float* mrow = mask + (long)b * SEQ;
    const int tid = threadIdx.x;

    float v[8];
    float lmax = -INFINITY;
    #pragma unroll
    for (int i = 0; i < 8; i++) {
        int c = tid + i * 256;
        v[i] = p[c] + (1.0f - mrow[c]) * -10000.0f;
        lmax = fmaxf(lmax, v[i]);
    }
    __shared__ float red[32];
    #pragma unroll
    for (int o = 16; o > 0; o >>= 1)
        lmax = fmaxf(lmax, __shfl_xor_sync(0xFFFFFFFFu, lmax, o));
    if ((tid & 31) == 0) red[tid >> 5] = lmax;
    __syncthreads();
    if (tid < 32) {
        float m = (tid < 8) ? red[tid] : -INFINITY;
        #pragma unroll
        for (int o = 4; o > 0; o >>= 1)
            m = fmaxf(m, __shfl_xor_sync(0xFFFFFFFFu, m, o));
        if (tid == 0) red[0] = m;
    }
    __syncthreads();
    const float rmax = red[0];

    float lsum = 0.0f;
    #pragma unroll
    for (int i = 0; i < 8; i++) {
        v[i] = __expf(v[i] - rmax);
        lsum += v[i];
    }
    #pragma unroll
    for (int o = 16; o > 0; o >>= 1)
        lsum += __shfl_xor_sync(0xFFFFFFFFu, lsum, o);
    __syncthreads();
    if ((tid & 31) == 0) red[tid >> 5] = lsum;
    __syncthreads();
    if (tid < 32) {
        float s = (tid < 8) ? red[tid] : 0.0f;
        #pragma unroll
        for (int o = 4; o > 0; o >>= 1)
            s += __shfl_xor_sync(0xFFFFFFFFu, s, o);
        if (tid == 0) red[0] = s;
    }
    __syncthreads();
    const float inv = 1.0f / red[0];

    #pragma unroll
    for (int i = 0; i < 8; i++) {
        int c = tid + i * 256;
        float x = v[i] * inv;
        __nv_bfloat16 h = __float2bfloat16(x);
        __nv_bfloat16 l = __float2bfloat16(x - __bfloat162float(h));
        ph[(long)row * SEQ + c] = h;
        pl[(long)row * SEQ + c] = l;
    }
}

// ---------------------------------------------------------------------------
extern "C" void kernel_launch(void* const* d_in, const int* in_sizes, int n_in,
                              void* d_out, int out_size)
{
    const float* qkv  = (const float*)d_in[0];
    const float* mask = (const float*)d_in[1];
    const float* W    = (const float*)d_in[2];
    const float* bqkv = (const float*)d_in[3];
    float* out = (float*)d_out;

    float *proj, *scores;
    __nv_bfloat16 *qkvh, *qkvl, *wth, *wtl, *qh, *ql, *kh, *kl, *pph, *ppl, *vth, *vtl;
    cudaGetSymbolAddress((void**)&proj, g_proj);
    cudaGetSymbolAddress((void**)&scores, g_scores);
    cudaGetSymbolAddress((void**)&qkvh, g_qkv_h);  cudaGetSymbolAddress((void**)&qkvl, g_qkv_l);
    cudaGetSymbolAddress((void**)&wth, g_wt_h);    cudaGetSymbolAddress((void**)&wtl, g_wt_l);
    cudaGetSymbolAddress((void**)&qh, g_q_h);      cudaGetSymbolAddress((void**)&ql, g_q_l);
    cudaGetSymbolAddress((void**)&kh, g_k_h);      cudaGetSymbolAddress((void**)&kl, g_k_l);
    cudaGetSymbolAddress((void**)&pph, g_p_h);     cudaGetSymbolAddress((void**)&ppl, g_p_l);
    cudaGetSymbolAddress((void**)&vth, g_vt_h);    cudaGetSymbolAddress((void**)&vtl, g_vt_l);

    cudaFuncSetAttribute(gemm_mma_kernel,
                         cudaFuncAttributeMaxDynamicSharedMemorySize, GEMM_SMEM);

    // 1) split qkv -> bf16 hi/lo
    split_kernel<<<(long)MROWS * (HID / 4) / 256, 256>>>(qkv, HID, qkvh, qkvl, HID, HID / 4);
    // 2) W [1024,3072] -> W^T [3072,1024] hi/lo
    transpose_split_kernel<<<dim3(NQKV / 32, HID / 32, 1), 256>>>(W, 0, NQKV, wth, wtl, 0, HID);
    // 3) proj GEMM (M=8192, N=3072, K=1024): Q/K cols fused-split to qh/ql/kh/kl,
    //    V cols -> proj fp32
    gemm_mma_kernel<<<dim3(NQKV / 128, MROWS / 128, 1), 256, GEMM_SMEM>>>(
        qkvh, qkvl, wth, wtl, proj, bqkv, qh, ql, kh, kl,
        HID, HID, HID, NQKV, 0, 0, 0, 1.0f);
    // 4) V slices -> V^T per batch [1024,2048] hi/lo
    transpose_split_kernel<<<dim3(HID / 32, SEQ / 32, BATCH), 256>>>(
        proj + 2 * HID, (long)SEQ * NQKV, NQKV, vth, vtl, (long)HID * SEQ, SEQ);
    // 5) scores[b] = (1/32) * Q_b @ K_b^T   (M=2048, N=2048, K=1024)
    gemm_mma_kernel<<<dim3(SEQ / 128, SEQ / 128, BATCH), 256, GEMM_SMEM>>>(
        qh, ql, kh, kl, scores, nullptr, nullptr, nullptr, nullptr, nullptr,
        HID, HID, HID, SEQ,
        (long)SEQ * HID, (long)SEQ * HID, (long)SEQ * SEQ, 1.0f / 32.0f);
    // 6) softmax rows + split P -> bf16 hi/lo
    softmax_split_kernel<<<BATCH * SEQ, 256>>>(scores, mask, pph, ppl);
    // 7) out[b] = P_b @ V_b   (M=2048, N=1024, K=2048)
    gemm_mma_kernel<<<dim3(HID / 128, SEQ / 128, BATCH), 256, GEMM_SMEM>>>(
        pph, ppl, vth, vtl, out, nullptr, nullptr, nullptr, nullptr, nullptr,
        SEQ, SEQ, SEQ, HID,
        (long)SEQ * SEQ, (long)HID * SEQ, (long)SEQ * HID, 1.0f);
}